// round 16
// baseline (speedup 1.0000x reference)
#include <cuda_runtime.h>
#include <stdint.h>

// SpikeFP32GELUExact — uniform relaxed-fp64 path, branchless DDIV-free mimic.
//
// R14 post-mortem: mimic (x<0, em<2^-17) is per-LANE (~10%), so ~96% of warps
// executed BOTH the divergent __ddiv_rn mimic and the accurate path. R16 makes
// the mimic uniform + cheap via the identity (reference's rounding sequence):
//   d1=RN(em-1)=-1+e1, w1=RN(em+1)=1+e2  (e1,e2 = em on 2^-53 / 2^-52 grids)
//   num=RN(w1+d1)=e1+e2 EXACT;  1+th = round_{2^-53}(num/(1+e2))
// computed as u=num*rc (shared Newton reciprocal), s=RN(u-1) does the grid
// rounding, h=1+s exact (Sterbenz), ym=0.5*RN(x*h). Reproduces the reference's
// cancellation noise and -0.0 saturation bit-for-bit (stray-flip exp < 0.1).
// Saturation |2z|>=80: analytic (-0.0 / identity). Accurate path + integer
// boundary window (2^18 units) + exact fp64 replica fallback: unchanged (R13/15).

__device__ double g_T[64];

__global__ void fill_table_kernel() {
    int j = threadIdx.x;
    if (j < 64) g_T[j] = exp2((double)j * 0.015625);   // 2^(j/64)
}

constexpr double SHIFT  = 6755399441055744.0;           // 1.5 * 2^52
constexpr double INVL64 = 92.33248261689366;            // 64 / ln2
constexpr double L64HI  = 0.6931471805599453 / 64.0;    // double(ln2)/64, exact scale
constexpr double L64LO  = 2.3190468138462996e-17 / 64.0;
constexpr double K2     = 2.0 * 0.7978845608028654;     // exact doubling

// Exact replica of the reference fp64 op sequence (R10: proven bit-perfect).
__device__ __noinline__ uint32_t gelu_exact_ref(float xf) {
    double xd  = (double)xf;
    double x2d = __dmul_rn(xd, xd);
    double x3d = __dmul_rn(x2d, xd);
    double ind = __dadd_rn(xd, __dmul_rn(0.044715, x3d));
    double twz = __dmul_rn(2.0, __dmul_rn(0.7978845608028654, ind));
    double e   = exp(twz);
    double th  = __ddiv_rn(__dadd_rn(e, -1.0), __dadd_rn(e, 1.0));
    double yd  = __dmul_rn(0.5, __dmul_rn(xd, __dadd_rn(1.0, th)));
    return __float_as_uint(__double2float_rn(yd));
}

__device__ __forceinline__ uint32_t gelu_bits(uint32_t ux, const double* __restrict__ sT) {
    const float  xf = __uint_as_float(ux);
    const double x  = (double)xf;

    // two_z: RN((2c)*inner) == ref's RN(2*RN(c*inner)); inner FMA dev <= 1 ulp.
    const double x3    = __dmul_rn(__dmul_rn(x, x), x);
    const double inner = __fma_rn(0.044715, x3, x);
    const double two_z = __dmul_rn(K2, inner);

    const int ihi = __double2hiint(two_z);
    const int iah = ihi & 0x7fffffff;
    if (iah >= 0x40540000) {                            // |2z| >= 80, inf, nan
        if (iah >= 0x7ff00000) return gelu_exact_ref(xf);
        return (ihi < 0) ? 0x80000000u : ux;            // forced -0.0 / identity
    }

    // em = exp(-|2z|): shift-trick k, 2-FMA Cody-Waite
    const double w  = __hiloint2double(iah | (int)0x80000000, __double2loint(two_z));
    const double tt = __fma_rn(w, INVL64, SHIFT);
    const int    k  = __double2loint(tt);
    const double kd = (double)k;                        // exact I2F
    double r = __fma_rn(kd, -L64HI, w);
    r = __fma_rn(kd, -L64LO, r);                        // |r| <= ln2/128, err ~2^-59

    // e^r = 1 + s, s = r + r^2/2 + r^2*(r*c); c in fp32 (err scaled by r^2)
    const float rf  = (float)r;
    const float cf  = fmaf(rf, fmaf(rf, 8.3333333e-3f, 4.1666667e-2f), 0.16666667f);
    const float rcf = __fmul_rn(rf, cf);                // ~ r/6
    const double r2 = __dmul_rn(r, r);
    const double s1 = __fma_rn(0.5, r2, r);
    const double s  = __fma_rn(r2, (double)rcf, s1);    // abs err ~2^-47.5

    double T = sT[k & 63];
    T = __hiloint2double(__double2hiint(T) + ((k >> 6) << 20), __double2loint(T));
    const double em = __fma_rn(T, s, T);                // T*(1+s), rel err ~2^-45

    // Shared reciprocal: rc ~ 1/(1+em), rel err ~2^-48 (frcp_rn seed 2^-24 + 1 Newton)
    const double w1 = __dadd_rn(em, 1.0);               // = 1+e2 exactly
    double rc = (double)__frcp_rn((float)w1);
    rc = __dmul_rn(rc, __fma_rn(-w1, rc, 2.0));

    // Branchless mimic (valid when em < 2^-17): reference's deep-negative rounding.
    const double d1  = __dadd_rn(em, -1.0);             // = -1+e1 exactly
    const double num = __dadd_rn(w1, d1);               // = e1+e2 EXACT
    const double u   = __dmul_rn(num, rc);              // (e1+e2)/(1+e2), err ~u*2^-48
    const double sm  = __dadd_rn(u, -1.0);              // rounds u onto 2^-53 grid
    const double h   = __dadd_rn(1.0, sm);              // exact (Sterbenz); ->0 if u<2^-54
    const double ym  = __dmul_rn(0.5, __dmul_rn(x, h));

    if (ihi < 0 && __double2hiint(em) < 0x3EE00000)     // x<0 and em < 2^-17
        return __float_as_uint(__double2float_rn(ym));

    // Accurate path: y = x*u/(1+em), u = (x>=0 ? 1 : em)
    const double nmr = (ihi < 0) ? __dmul_rn(x, em) : x;
    const double y   = __dmul_rn(nmr, rc);

    const float f = __double2float_rn(y);
    uint32_t bits_y = __float_as_uint(f);

    // Integer boundary window on y's fp64 mantissa tail (midpoint at 2^28 mod 2^29).
    const int tail = __double2loint(y) & 0x1fffffff;
    int dist = tail - 0x10000000;
    dist = (dist < 0) ? -dist : dist;
    if (dist < 0x40000 || (bits_y & 0x7f800000u) == 0u)
        return gelu_exact_ref(xf);
    return bits_y;
}

__global__ void __launch_bounds__(256)
spike_gelu_kernel(const uint32_t* __restrict__ xu,
                  uint32_t* __restrict__ outu,
                  int n_elem)
{
    __shared__ double sT[64];
    if (threadIdx.x < 64) sT[threadIdx.x] = g_T[threadIdx.x];
    __syncthreads();

    const int lane        = threadIdx.x & 31;
    const int warp_global = (blockIdx.x * blockDim.x + threadIdx.x) >> 5;
    const int base        = warp_global * 32;
    if (base >= n_elem) return;

    const size_t off = (size_t)base * 32;

    // Load: lane l reads bit-position l of element (base+i). Fully coalesced.
    uint32_t v[32];
#pragma unroll
    for (int i = 0; i < 32; i++)
        v[i] = xu[off + (size_t)i * 32 + lane];

    // Transpose via ballot: bit 0 = MSB after brev.
    uint32_t myu = 0;
#pragma unroll
    for (int i = 0; i < 32; i++) {
        unsigned b = __ballot_sync(0xffffffffu, v[i] != 0u);
        uint32_t u = __brev(b);
        if (lane == i) myu = u;
    }

    const uint32_t uy = gelu_bits(myu, sT);

    // Store: broadcast element i's word; lane l writes bit l.
#pragma unroll
    for (int i = 0; i < 32; i++) {
        uint32_t ui  = __shfl_sync(0xffffffffu, uy, i);
        uint32_t bit = (ui >> (31 - lane)) & 1u;
        outu[off + (size_t)i * 32 + lane] = bit ? 0x3F800000u : 0u;
    }
}

extern "C" void kernel_launch(void* const* d_in, const int* in_sizes, int n_in,
                              void* d_out, int out_size)
{
    const uint32_t* x   = (const uint32_t*)d_in[0];
    uint32_t*       out = (uint32_t*)d_out;

    const int n_elem  = in_sizes[0] / 32;               // 1024*4096
    const int threads = 256;
    const int blocks  = (n_elem + 255) / 256;

    fill_table_kernel<<<1, 64>>>();
    spike_gelu_kernel<<<blocks, threads>>>(x, out, n_elem);
}

// round 17
// speedup vs baseline: 1.2614x; 1.2614x over previous
#include <cuda_runtime.h>
#include <stdint.h>

// SpikeFP32GELUExact — R17: R14 structure (divergent mimic, best measured 256.8us)
// + R16's hardware-proven DDIV-free mimic formula + 1-FMA Cody-Waite.
//
// R16 post-mortem: uniform mimic = +7 fp64 ops on 100% of warps > divergent
// DDIV on 46% of warps => regression. Mimic band is x<~-4.15 (P(lane)~1.9%,
// P(warp)~46%). R17 keeps the branch but the body reuses the shared Newton
// reciprocal rc ~ 1/(1+em):
//   d1=RN(em-1), num=RN(w1+d1)=e1+e2 exact, u=num*rc (err u*2^-48),
//   s=RN(u-1) performs the reference's 2^-53 grid rounding, h=1+s exact
//   (Sterbenz; ->0 when u<2^-54 reproducing -0.0), ym=0.5*RN(x*h).
// Proven rel_err 0.0 on HW in R16. Cody-Waite lo term dropped: |k|*L64LO
// <= 2^-48.4 abs in r -> em rel err ~2^-45, >=2^9 headroom vs all margins.

__device__ double g_T[64];

__global__ void fill_table_kernel() {
    int j = threadIdx.x;
    if (j < 64) g_T[j] = exp2((double)j * 0.015625);   // 2^(j/64)
}

constexpr double SHIFT  = 6755399441055744.0;           // 1.5 * 2^52
constexpr double INVL64 = 92.33248261689366;            // 64 / ln2
constexpr double L64HI  = 0.6931471805599453 / 64.0;    // double(ln2)/64, exact scale
constexpr double K2     = 2.0 * 0.7978845608028654;     // exact doubling

// Exact replica of the reference fp64 op sequence (R10: proven bit-perfect).
__device__ __noinline__ uint32_t gelu_exact_ref(float xf) {
    double xd  = (double)xf;
    double x2d = __dmul_rn(xd, xd);
    double x3d = __dmul_rn(x2d, xd);
    double ind = __dadd_rn(xd, __dmul_rn(0.044715, x3d));
    double twz = __dmul_rn(2.0, __dmul_rn(0.7978845608028654, ind));
    double e   = exp(twz);
    double th  = __ddiv_rn(__dadd_rn(e, -1.0), __dadd_rn(e, 1.0));
    double yd  = __dmul_rn(0.5, __dmul_rn(xd, __dadd_rn(1.0, th)));
    return __float_as_uint(__double2float_rn(yd));
}

__device__ __forceinline__ uint32_t gelu_bits(uint32_t ux, const double* __restrict__ sT) {
    const float  xf = __uint_as_float(ux);
    const double x  = (double)xf;

    // two_z: RN((2c)*inner) == ref's RN(2*RN(c*inner)); inner FMA dev <= 1 ulp.
    const double x3    = __dmul_rn(__dmul_rn(x, x), x);
    const double inner = __fma_rn(0.044715, x3, x);
    const double two_z = __dmul_rn(K2, inner);

    const int ihi = __double2hiint(two_z);
    const int iah = ihi & 0x7fffffff;
    if (iah >= 0x40540000) {                            // |2z| >= 80, inf, nan
        if (iah >= 0x7ff00000) return gelu_exact_ref(xf);
        return (ihi < 0) ? 0x80000000u : ux;            // forced -0.0 / identity
    }

    // em = exp(-|2z|): shift-trick k, 1-FMA Cody-Waite (lo term <= 2^-48.4 dropped)
    const double w  = __hiloint2double(iah | (int)0x80000000, __double2loint(two_z));
    const double tt = __fma_rn(w, INVL64, SHIFT);
    const int    k  = __double2loint(tt);
    const double kd = (double)k;                        // exact I2F
    const double r  = __fma_rn(kd, -L64HI, w);          // |r| <= ln2/128

    // e^r = 1 + s, s = r + r^2/2 + r^2*(r*c); c in fp32 (err scaled by r^2)
    const float rf  = (float)r;
    const float cf  = fmaf(rf, fmaf(rf, 8.3333333e-3f, 4.1666667e-2f), 0.16666667f);
    const float rcf = __fmul_rn(rf, cf);                // ~ r/6
    const double r2 = __dmul_rn(r, r);
    const double s1 = __fma_rn(0.5, r2, r);
    const double s  = __fma_rn(r2, (double)rcf, s1);    // abs err ~2^-47.5

    double T = sT[k & 63];
    T = __hiloint2double(__double2hiint(T) + ((k >> 6) << 20), __double2loint(T));
    const double em = __fma_rn(T, s, T);                // T*(1+s), rel err ~2^-45

    // Shared reciprocal rc ~ 1/(1+em), rel err ~2^-48 (used by BOTH paths).
    const double w1 = __dadd_rn(em, 1.0);               // = 1+e2 exactly
    double rc = (double)__frcp_rn((float)w1);
    rc = __dmul_rn(rc, __fma_rn(-w1, rc, 2.0));

    // Divergent mimic (x<0, em<2^-17, ~46% of warps, ~1.9% of lanes):
    // reference's deep-negative rounding sequence, DDIV-free (R16-proven).
    if (ihi < 0 && __double2hiint(em) < 0x3EE00000) {
        const double d1  = __dadd_rn(em, -1.0);         // = -1+e1 exactly
        const double num = __dadd_rn(w1, d1);           // = e1+e2 EXACT
        const double u   = __dmul_rn(num, rc);          // err ~u*2^-48
        const double sm  = __dadd_rn(u, -1.0);          // 2^-53 grid rounding
        const double h   = __dadd_rn(1.0, sm);          // exact; ->0 if u<2^-54
        const double ym  = __dmul_rn(0.5, __dmul_rn(x, h));
        return __float_as_uint(__double2float_rn(ym));
    }

    // Accurate path: y = x*u/(1+em), u = (x>=0 ? 1 : em)
    const double nmr = (ihi < 0) ? __dmul_rn(x, em) : x;
    const double y   = __dmul_rn(nmr, rc);

    const float f = __double2float_rn(y);
    uint32_t bits_y = __float_as_uint(f);

    // Integer boundary window on y's fp64 mantissa tail (midpoint at 2^28 mod 2^29).
    const int tail = __double2loint(y) & 0x1fffffff;
    int dist = tail - 0x10000000;
    dist = (dist < 0) ? -dist : dist;
    if (dist < 0x40000 || (bits_y & 0x7f800000u) == 0u)
        return gelu_exact_ref(xf);
    return bits_y;
}

__global__ void __launch_bounds__(256)
spike_gelu_kernel(const uint32_t* __restrict__ xu,
                  uint32_t* __restrict__ outu,
                  int n_elem)
{
    __shared__ double sT[64];
    if (threadIdx.x < 64) sT[threadIdx.x] = g_T[threadIdx.x];
    __syncthreads();

    const int lane        = threadIdx.x & 31;
    const int warp_global = (blockIdx.x * blockDim.x + threadIdx.x) >> 5;
    const int base        = warp_global * 32;
    if (base >= n_elem) return;

    const size_t off = (size_t)base * 32;

    // Load: lane l reads bit-position l of element (base+i). Fully coalesced.
    uint32_t v[32];
#pragma unroll
    for (int i = 0; i < 32; i++)
        v[i] = xu[off + (size_t)i * 32 + lane];

    // Transpose via ballot: bit 0 = MSB after brev.
    uint32_t myu = 0;
#pragma unroll
    for (int i = 0; i < 32; i++) {
        unsigned b = __ballot_sync(0xffffffffu, v[i] != 0u);
        uint32_t u = __brev(b);
        if (lane == i) myu = u;
    }

    const uint32_t uy = gelu_bits(myu, sT);

    // Store: broadcast element i's word; lane l writes bit l.
#pragma unroll
    for (int i = 0; i < 32; i++) {
        uint32_t ui  = __shfl_sync(0xffffffffu, uy, i);
        uint32_t bit = (ui >> (31 - lane)) & 1u;
        outu[off + (size_t)i * 32 + lane] = bit ? 0x3F800000u : 0u;
    }
}

extern "C" void kernel_launch(void* const* d_in, const int* in_sizes, int n_in,
                              void* d_out, int out_size)
{
    const uint32_t* x   = (const uint32_t*)d_in[0];
    uint32_t*       out = (uint32_t*)d_out;

    const int n_elem  = in_sizes[0] / 32;               // 1024*4096
    const int threads = 256;
    const int blocks  = (n_elem + 255) / 256;

    fill_table_kernel<<<1, 64>>>();
    spike_gelu_kernel<<<blocks, threads>>>(x, out, n_elem);
}